// round 9
// baseline (speedup 1.0000x reference)
#include <cuda_runtime.h>
#include <cuda_bf16.h>
#include <cstdint>

#define N_ALPHA 0.05f
#define N_BETA  0.95f
#define BC_TOT  128
#define NN      1024
#define HID     20
#define KCH     32            // K per chunk
#define NCHUNK  (NN / KCH)    // 32
#define TM      128           // rows per CTA

// A tile: 128 rows x 32 bf16, rows padded to 80B -> conflict-free ldmatrix
#define A_T     (128 * 80)    // 10240 B
#define B_T     (32 * 80)     // 2560 B
#define STAGE   (2 * A_T + 2 * B_T)   // 25600
#define OFF_AH  0
#define OFF_AL  A_T
#define OFF_BH  (2 * A_T)
#define OFF_BL  (2 * A_T + B_T)
#define SMEM_SZ (2 * STAGE)   // 51200

// scratch: h0..h3
__device__ float g_h[4][BC_TOT * NN * HID];

static __device__ __forceinline__ unsigned smem_u32(const void* p) {
    unsigned a;
    asm("{ .reg .u64 t; cvta.to.shared.u64 t, %1; cvt.u32.u64 %0, t; }"
        : "=r"(a) : "l"(p));
    return a;
}
static __device__ __forceinline__ unsigned long long fma2(unsigned long long a,
                                                          unsigned long long b,
                                                          unsigned long long c) {
    unsigned long long d;
    asm("fma.rn.f32x2 %0, %1, %2, %3;" : "=l"(d) : "l"(a), "l"(b), "l"(c));
    return d;
}
static __device__ __forceinline__ unsigned long long pack2(float x, float y) {
    unsigned long long d;
    asm("mov.b64 %0, {%1, %2};" : "=l"(d) : "f"(x), "f"(y));
    return d;
}
static __device__ __forceinline__ float2 unpack2(unsigned long long v) {
    float2 f;
    asm("mov.b64 {%0, %1}, %2;" : "=f"(f.x), "=f"(f.y) : "l"(v));
    return f;
}
static __device__ __forceinline__ void ldm_x4(uint32_t* r, uint32_t addr) {
    asm volatile("ldmatrix.sync.aligned.m8n8.x4.shared.b16 {%0,%1,%2,%3}, [%4];"
                 : "=r"(r[0]), "=r"(r[1]), "=r"(r[2]), "=r"(r[3]) : "r"(addr));
}
static __device__ __forceinline__ void ldm_x2t(uint32_t* r, uint32_t addr) {
    asm volatile("ldmatrix.sync.aligned.m8n8.x2.trans.shared.b16 {%0,%1}, [%2];"
                 : "=r"(r[0]), "=r"(r[1]) : "r"(addr));
}
static __device__ __forceinline__ void mma_bf16(float* c, const uint32_t* a,
                                                const uint32_t* b) {
    asm volatile(
        "mma.sync.aligned.m16n8k16.row.col.f32.bf16.bf16.f32 "
        "{%0,%1,%2,%3}, {%4,%5,%6,%7}, {%8,%9}, {%0,%1,%2,%3};"
        : "+f"(c[0]), "+f"(c[1]), "+f"(c[2]), "+f"(c[3])
        : "r"(a[0]), "r"(a[1]), "r"(a[2]), "r"(a[3]), "r"(b[0]), "r"(b[1]));
}
// hi = truncate-to-bf16 pair; lo = exact residual rounded to bf16 pair
static __device__ __forceinline__ void split2(float x, float y,
                                              uint32_t& hp, uint32_t& lp) {
    uint32_t u0 = __float_as_uint(x), u1 = __float_as_uint(y);
    asm("prmt.b32 %0, %1, %2, 0x7632;" : "=r"(hp) : "r"(u0), "r"(u1));
    float l0 = x - __uint_as_float(u0 & 0xFFFF0000u);
    float l1 = y - __uint_as_float(u1 & 0xFFFF0000u);
    asm("cvt.rn.bf16x2.f32 %0, %1, %2;" : "=r"(lp) : "f"(l1), "f"(l0));
}

// ---------------------------------------------------------------------------
// h0[bc][n][j] = sum_i x[b][i][n][c] * Ws[i][j] + bs[j]
// ---------------------------------------------------------------------------
__global__ void h0_kernel(const float* __restrict__ x,
                          const float* __restrict__ Ws,
                          const float* __restrict__ bs) {
    __shared__ float wsm[32 * HID];
    __shared__ float bsm[HID];
    int tid = threadIdx.x;
    for (int i = tid; i < 32 * HID; i += 256) wsm[i] = Ws[i];
    if (tid < HID) bsm[tid] = bs[tid];
    __syncthreads();

    int r = blockIdx.x * 256 + tid;
    int c = r & 15;
    int n = (r >> 4) & 1023;
    int b = r >> 14;

    unsigned long long acc[10];
    const unsigned long long* bp = (const unsigned long long*)bsm;
#pragma unroll
    for (int j = 0; j < 10; j++) acc[j] = bp[j];

    const float* xp = x + (size_t)b * 32 * 16384 + n * 16 + c;
#pragma unroll
    for (int i = 0; i < 32; i++) {
        float xv = xp[(size_t)i * 16384];
        unsigned long long xv2 = pack2(xv, xv);
        const unsigned long long* wr = (const unsigned long long*)&wsm[i * HID];
#pragma unroll
        for (int j = 0; j < 10; j++) acc[j] = fma2(xv2, wr[j], acc[j]);
    }
    int bc = b * 16 + c;
    float* o = &g_h[0][((size_t)bc * NN + n) * HID];
#pragma unroll
    for (int j = 0; j < 10; j++) {
        float2 f = unpack2(acc[j]);
        o[2 * j] = f.x; o[2 * j + 1] = f.y;
    }
}

// ---------------------------------------------------------------------------
// propagation via mma.sync, bf16 hi/lo emulated fp32, 2m x 2k warp split:
//   warp (mg, kg): rows [mg*64, mg*64+64), k-halfchunk kg -> B ldm 4x less.
//   D[v][n<20] = sum_w adj[v][w] h[w][n] ; D[v][20] = rowsum (ones col)
//   h_dst[v] = alpha*h0[v] + beta*(D[v][:20] + h_src[v]) / (D[v][20] + 1)
// ---------------------------------------------------------------------------
__global__ void __launch_bounds__(128, 4)
prop_mma(const float* __restrict__ adj, int src, int dst) {
    extern __shared__ char smem[];
    const uint32_t sb = smem_u32(smem);
    int tid = threadIdx.x;
    int lane = tid & 31, wid = tid >> 5;
    int mg = wid >> 1, kg = wid & 1;
    int rowbase = blockIdx.x * TM;
    int bc = blockIdx.y;

    const float* A = adj + ((size_t)bc << 20) + ((size_t)rowbase << 10);
    const float* H = &g_h[src][(size_t)bc * (NN * HID)];

    // zero B regions (pad cols stay zero); ones col n=20 (byte 40) in Bhi
    for (int st = 0; st < 2; st++) {
        uint32_t* bb = (uint32_t*)(smem + st * STAGE + OFF_BH);
        for (int i = tid; i < (2 * B_T) / 4; i += 128) bb[i] = 0;
    }
    __syncthreads();
    if (tid < 32) {
        *(uint16_t*)(smem + 0 * STAGE + OFF_BH + tid * 80 + 40) = 0x3F80;
        *(uint16_t*)(smem + 1 * STAGE + OFF_BH + tid * 80 + 40) = 0x3F80;
    }

    // A granules: g = tid + p*128 -> row g>>3, col (g&7)*4
    bool hasb2 = tid < 32;

    float acc[4][3][4];
#pragma unroll
    for (int f = 0; f < 4; f++)
#pragma unroll
        for (int nt = 0; nt < 3; nt++)
#pragma unroll
            for (int q = 0; q < 4; q++) acc[f][nt][q] = 0.f;

    // prefetch chunk 0
    float4 abuf[8], bbuf, bbuf2;
#pragma unroll
    for (int p = 0; p < 8; p++) {
        int g = tid + p * 128;
        abuf[p] = __ldcs((const float4*)(A + (size_t)(g >> 3) * NN + ((g & 7) << 2)));
    }
    bbuf = *(const float4*)(H + (size_t)(tid / 5) * HID + (tid % 5) * 4);
    if (hasb2) {
        int g = 128 + tid;
        bbuf2 = *(const float4*)(H + (size_t)(g / 5) * HID + (g % 5) * 4);
    }

    const uint32_t a_lm_base = (uint32_t)(mg * 64 + (lane & 15)) * 80 +
                               (uint32_t)(kg * 32 + ((lane >> 4) << 4));
    const uint32_t b_lm_base = (uint32_t)(kg * 16 + (lane & 15)) * 80;

#pragma unroll 1
    for (int i = 0; i < NCHUNK; i++) {
        int st = i & 1;
        uint32_t stb = sb + st * STAGE;
        __syncthreads();   // stage st free (readers of iter i-2 done)

        // ---- split + STS A (hi + lo)
#pragma unroll
        for (int p = 0; p < 8; p++) {
            int g = tid + p * 128;
            uint32_t hp0, lp0, hp1, lp1;
            split2(abuf[p].x, abuf[p].y, hp0, lp0);
            split2(abuf[p].z, abuf[p].w, hp1, lp1);
            uint32_t off = (uint32_t)(g >> 3) * 80 + (uint32_t)((g & 7) << 2) * 2;
            *(uint2*)(smem + st * STAGE + OFF_AH + off) = make_uint2(hp0, hp1);
            *(uint2*)(smem + st * STAGE + OFF_AL + off) = make_uint2(lp0, lp1);
        }
        // ---- split + STS B
        {
            uint32_t hp0, lp0, hp1, lp1;
            split2(bbuf.x, bbuf.y, hp0, lp0);
            split2(bbuf.z, bbuf.w, hp1, lp1);
            uint32_t off = (uint32_t)(tid / 5) * 80 + (uint32_t)((tid % 5) * 4) * 2;
            *(uint2*)(smem + st * STAGE + OFF_BH + off) = make_uint2(hp0, hp1);
            *(uint2*)(smem + st * STAGE + OFF_BL + off) = make_uint2(lp0, lp1);
            if (hasb2) {
                int g = 128 + tid;
                split2(bbuf2.x, bbuf2.y, hp0, lp0);
                split2(bbuf2.z, bbuf2.w, hp1, lp1);
                off = (uint32_t)(g / 5) * 80 + (uint32_t)((g % 5) * 4) * 2;
                *(uint2*)(smem + st * STAGE + OFF_BH + off) = make_uint2(hp0, hp1);
                *(uint2*)(smem + st * STAGE + OFF_BL + off) = make_uint2(lp0, lp1);
            }
        }

        // ---- prefetch chunk i+1 (hidden behind mma below)
        if (i + 1 < NCHUNK) {
            const float* ap = A + (i + 1) * KCH;
#pragma unroll
            for (int p = 0; p < 8; p++) {
                int g = tid + p * 128;
                abuf[p] = __ldcs((const float4*)(ap + (size_t)(g >> 3) * NN +
                                                 ((g & 7) << 2)));
            }
            const float* hp2 = H + (size_t)(i + 1) * (KCH * HID);
            bbuf = *(const float4*)(hp2 + (size_t)(tid / 5) * HID + (tid % 5) * 4);
            if (hasb2) {
                int g = 128 + tid;
                bbuf2 = *(const float4*)(hp2 + (size_t)(g / 5) * HID + (g % 5) * 4);
            }
        }
        __syncthreads();   // stage st fully written

        // ---- B frags once per chunk (this warp's k16 half)
        uint32_t bh[3][2], bl[3][2];
        uint32_t brow = stb + OFF_BH + b_lm_base;
#pragma unroll
        for (int nt = 0; nt < 3; nt++) {
            ldm_x2t(bh[nt], brow + nt * 16);
            ldm_x2t(bl[nt], brow + nt * 16 + B_T);
        }
        // ---- A frags per m16 block, 9 MMAs each
        uint32_t aaddr = stb + OFF_AH + a_lm_base;
#pragma unroll
        for (int f = 0; f < 4; f++) {
            uint32_t ah[4], al[4];
            ldm_x4(ah, aaddr + (uint32_t)(f * 16) * 80);
            ldm_x4(al, aaddr + (uint32_t)(f * 16) * 80 + A_T);
#pragma unroll
            for (int nt = 0; nt < 3; nt++) {
                mma_bf16(acc[f][nt], ah, bh[nt]);
                mma_bf16(acc[f][nt], ah, bl[nt]);
                mma_bf16(acc[f][nt], al, bh[nt]);
            }
        }
    }

    // ---- epilogue: k-partials -> smem [kg][128][28], reduce, combine
    __syncthreads();
    {
        float* ds = (float*)smem + (size_t)kg * (128 * 28);
        int r0 = lane >> 2;
        int c0 = (lane & 3) * 2;
#pragma unroll
        for (int f = 0; f < 4; f++) {
            int rbase = mg * 64 + f * 16;
#pragma unroll
            for (int nt = 0; nt < 3; nt++) {
                int c = nt * 8 + c0;
                *(float2*)&ds[(rbase + r0) * 28 + c] =
                    make_float2(acc[f][nt][0], acc[f][nt][1]);
                *(float2*)&ds[(rbase + r0 + 8) * 28 + c] =
                    make_float2(acc[f][nt][2], acc[f][nt][3]);
            }
        }
    }
    __syncthreads();
    {
        const float* d0 = (const float*)smem + (size_t)tid * 28;
        const float* d1 = d0 + 128 * 28;
        int v = rowbase + tid;
        float ir = 1.f / (d0[20] + d1[20] + 1.f);
        const float* hsr = H + (size_t)v * HID;
        const float* h0r = &g_h[0][(size_t)bc * (NN * HID) + (size_t)v * HID];
        float* outr = &g_h[dst][(size_t)bc * (NN * HID) + (size_t)v * HID];
        float res[20];
#pragma unroll
        for (int j = 0; j < 20; j++)
            res[j] = N_ALPHA * h0r[j] + N_BETA * (d0[j] + d1[j] + hsr[j]) * ir;
#pragma unroll
        for (int q = 0; q < 5; q++)
            ((float4*)outr)[q] = make_float4(res[4 * q], res[4 * q + 1],
                                             res[4 * q + 2], res[4 * q + 3]);
    }
}

// ---------------------------------------------------------------------------
// out[bc][n][o] = sum_{p,j} h_p[bc][n][j] * We[(p*20+j)][o] + be[o]
// ---------------------------------------------------------------------------
__global__ void __launch_bounds__(256) end_kernel(const float* __restrict__ We,
                                                  const float* __restrict__ be,
                                                  float* __restrict__ out) {
    __shared__ float wsm[80 * 32];
    __shared__ float bsm[32];
    __shared__ float hsm[256 * HID];
    int tid = threadIdx.x;
    for (int i = tid; i < 80 * 32; i += 256) wsm[i] = We[i];
    if (tid < 32) bsm[tid] = be[tid];

    int r0 = blockIdx.x * 256;

    unsigned long long acc[16];
    const unsigned long long* bp = (const unsigned long long*)bsm;
#pragma unroll
    for (int p = 0; p < 4; p++) {
        __syncthreads();
        const float4* src4 = (const float4*)(&g_h[p][0] + (size_t)r0 * HID);
#pragma unroll
        for (int k = 0; k < 5; k++)
            ((float4*)hsm)[tid + k * 256] = src4[tid + k * 256];
        __syncthreads();
        if (p == 0) {
#pragma unroll
            for (int o = 0; o < 16; o++) acc[o] = bp[o];
        }
        const float* hr = hsm + tid * HID;
#pragma unroll
        for (int j = 0; j < HID; j++) {
            float v = hr[j];
            unsigned long long v2 = pack2(v, v);
            const unsigned long long* wr =
                (const unsigned long long*)&wsm[(p * HID + j) * 32];
#pragma unroll
            for (int o = 0; o < 16; o++) acc[o] = fma2(v2, wr[o], acc[o]);
        }
    }

    float* op = out + ((size_t)r0 + tid) * 32;
#pragma unroll
    for (int o = 0; o < 16; o++) {
        float2 f = unpack2(acc[o]);
        op[2 * o] = f.x; op[2 * o + 1] = f.y;
    }
}

// ---------------------------------------------------------------------------
extern "C" void kernel_launch(void* const* d_in, const int* in_sizes, int n_in,
                              void* d_out, int out_size) {
    const float* x   = (const float*)d_in[0];
    const float* adj = (const float*)d_in[1];
    const float* Ws  = (const float*)d_in[2];
    const float* bs  = (const float*)d_in[3];
    const float* We  = (const float*)d_in[4];
    const float* be  = (const float*)d_in[5];
    float* out = (float*)d_out;

    cudaFuncSetAttribute(prop_mma, cudaFuncAttributeMaxDynamicSharedMemorySize,
                         SMEM_SZ);

    dim3 pgrid(NN / TM, BC_TOT);   // (8, 128) = 1024 CTAs

    h0_kernel<<<512, 256>>>(x, Ws, bs);
    prop_mma<<<pgrid, 128, SMEM_SZ>>>(adj, 0, 1);
    prop_mma<<<pgrid, 128, SMEM_SZ>>>(adj, 1, 2);
    prop_mma<<<pgrid, 128, SMEM_SZ>>>(adj, 2, 3);
    end_kernel<<<512, 256>>>(We, be, out);
}

// round 10
// speedup vs baseline: 1.0756x; 1.0756x over previous
#include <cuda_runtime.h>
#include <cuda_bf16.h>
#include <cstdint>

#define N_ALPHA 0.05f
#define N_BETA  0.95f
#define BC_TOT  128
#define NN      1024
#define HID     20
#define KCH     32            // K per chunk
#define NCHUNK  (NN / KCH)    // 32
#define TM      128           // rows per CTA

// A tile: 128 rows x 32 bf16, rows padded to 80B -> conflict-free ldmatrix
#define A_T     (128 * 80)    // 10240 B
#define B_T     (32 * 80)     // 2560 B
#define STAGE   (2 * A_T + 2 * B_T)   // 25600
#define OFF_AH  0
#define OFF_AL  A_T
#define OFF_BH  (2 * A_T)
#define OFF_BL  (2 * A_T + B_T)
#define SMEM_SZ (2 * STAGE)   // 51200

// scratch: h0..h3
__device__ float g_h[4][BC_TOT * NN * HID];

static __device__ __forceinline__ unsigned smem_u32(const void* p) {
    unsigned a;
    asm("{ .reg .u64 t; cvta.to.shared.u64 t, %1; cvt.u32.u64 %0, t; }"
        : "=r"(a) : "l"(p));
    return a;
}
static __device__ __forceinline__ unsigned long long fma2(unsigned long long a,
                                                          unsigned long long b,
                                                          unsigned long long c) {
    unsigned long long d;
    asm("fma.rn.f32x2 %0, %1, %2, %3;" : "=l"(d) : "l"(a), "l"(b), "l"(c));
    return d;
}
static __device__ __forceinline__ unsigned long long pack2(float x, float y) {
    unsigned long long d;
    asm("mov.b64 %0, {%1, %2};" : "=l"(d) : "f"(x), "f"(y));
    return d;
}
static __device__ __forceinline__ float2 unpack2(unsigned long long v) {
    float2 f;
    asm("mov.b64 {%0, %1}, %2;" : "=f"(f.x), "=f"(f.y) : "l"(v));
    return f;
}
static __device__ __forceinline__ void ldm_x4(uint32_t* r, uint32_t addr) {
    asm volatile("ldmatrix.sync.aligned.m8n8.x4.shared.b16 {%0,%1,%2,%3}, [%4];"
                 : "=r"(r[0]), "=r"(r[1]), "=r"(r[2]), "=r"(r[3]) : "r"(addr));
}
static __device__ __forceinline__ void ldm_x2t(uint32_t* r, uint32_t addr) {
    asm volatile("ldmatrix.sync.aligned.m8n8.x2.trans.shared.b16 {%0,%1}, [%2];"
                 : "=r"(r[0]), "=r"(r[1]) : "r"(addr));
}
static __device__ __forceinline__ void mma_bf16(float* c, const uint32_t* a,
                                                const uint32_t* b) {
    asm volatile(
        "mma.sync.aligned.m16n8k16.row.col.f32.bf16.bf16.f32 "
        "{%0,%1,%2,%3}, {%4,%5,%6,%7}, {%8,%9}, {%0,%1,%2,%3};"
        : "+f"(c[0]), "+f"(c[1]), "+f"(c[2]), "+f"(c[3])
        : "r"(a[0]), "r"(a[1]), "r"(a[2]), "r"(a[3]), "r"(b[0]), "r"(b[1]));
}
// hi = truncate-to-bf16 pair; lo = exact residual rounded to bf16 pair
static __device__ __forceinline__ void split2(float x, float y,
                                              uint32_t& hp, uint32_t& lp) {
    uint32_t u0 = __float_as_uint(x), u1 = __float_as_uint(y);
    asm("prmt.b32 %0, %1, %2, 0x7632;" : "=r"(hp) : "r"(u0), "r"(u1));
    float l0 = x - __uint_as_float(u0 & 0xFFFF0000u);
    float l1 = y - __uint_as_float(u1 & 0xFFFF0000u);
    asm("cvt.rn.bf16x2.f32 %0, %1, %2;" : "=r"(lp) : "f"(l1), "f"(l0));
}

// ---------------------------------------------------------------------------
// h0[bc][n][j] = sum_i x[b][i][n][c] * Ws[i][j] + bs[j]
// ---------------------------------------------------------------------------
__global__ void h0_kernel(const float* __restrict__ x,
                          const float* __restrict__ Ws,
                          const float* __restrict__ bs) {
    __shared__ float wsm[32 * HID];
    __shared__ float bsm[HID];
    int tid = threadIdx.x;
    for (int i = tid; i < 32 * HID; i += 256) wsm[i] = Ws[i];
    if (tid < HID) bsm[tid] = bs[tid];
    __syncthreads();

    int r = blockIdx.x * 256 + tid;
    int c = r & 15;
    int n = (r >> 4) & 1023;
    int b = r >> 14;

    unsigned long long acc[10];
    const unsigned long long* bp = (const unsigned long long*)bsm;
#pragma unroll
    for (int j = 0; j < 10; j++) acc[j] = bp[j];

    const float* xp = x + (size_t)b * 32 * 16384 + n * 16 + c;
#pragma unroll
    for (int i = 0; i < 32; i++) {
        float xv = xp[(size_t)i * 16384];
        unsigned long long xv2 = pack2(xv, xv);
        const unsigned long long* wr = (const unsigned long long*)&wsm[i * HID];
#pragma unroll
        for (int j = 0; j < 10; j++) acc[j] = fma2(xv2, wr[j], acc[j]);
    }
    int bc = b * 16 + c;
    float* o = &g_h[0][((size_t)bc * NN + n) * HID];
#pragma unroll
    for (int j = 0; j < 10; j++) {
        float2 f = unpack2(acc[j]);
        o[2 * j] = f.x; o[2 * j + 1] = f.y;
    }
}

// ---------------------------------------------------------------------------
// propagation via mma.sync, bf16 hi/lo emulated fp32.
// 256 threads = 8 warps in 4m x 2k: warp (mg, kg) owns rows [mg*32, mg*32+32)
// and k-halfchunk kg. B ldmatrix replication 8x -> 4x vs R7; A unchanged.
//   D[v][n<20] = sum_w adj[v][w] h[w][n] ; D[v][20] = rowsum (ones col)
//   h_dst[v] = alpha*h0[v] + beta*(D[v][:20] + h_src[v]) / (D[v][20] + 1)
// ---------------------------------------------------------------------------
__global__ void __launch_bounds__(256, 3)
prop_mma(const float* __restrict__ adj, int src, int dst) {
    extern __shared__ char smem[];
    const uint32_t sb = smem_u32(smem);
    int tid = threadIdx.x;
    int lane = tid & 31, wid = tid >> 5;
    int mg = wid >> 1, kg = wid & 1;
    int rowbase = blockIdx.x * TM;
    int bc = blockIdx.y;

    const float* A = adj + ((size_t)bc << 20) + ((size_t)rowbase << 10);
    const float* H = &g_h[src][(size_t)bc * (NN * HID)];

    // zero B regions (pad cols stay zero); ones col n=20 (byte 40) in Bhi
    for (int st = 0; st < 2; st++) {
        uint32_t* bb = (uint32_t*)(smem + st * STAGE + OFF_BH);
        for (int i = tid; i < (2 * B_T) / 4; i += 256) bb[i] = 0;
    }
    __syncthreads();
    if (tid < 32) {
        *(uint16_t*)(smem + 0 * STAGE + OFF_BH + tid * 80 + 40) = 0x3F80;
        *(uint16_t*)(smem + 1 * STAGE + OFF_BH + tid * 80 + 40) = 0x3F80;
    }

    bool hasb = tid < 160;
    int bk = tid / 5, bc4 = (tid % 5) * 4;

    float acc[2][3][4];
#pragma unroll
    for (int f = 0; f < 2; f++)
#pragma unroll
        for (int nt = 0; nt < 3; nt++)
#pragma unroll
            for (int q = 0; q < 4; q++) acc[f][nt][q] = 0.f;

    // prefetch chunk 0 (A granules: g = tid + p*256 -> row g>>3, col (g&7)*4)
    float4 abuf[4], bbuf;
#pragma unroll
    for (int p = 0; p < 4; p++) {
        int g = tid + p * 256;
        abuf[p] = __ldcs((const float4*)(A + (size_t)(g >> 3) * NN + ((g & 7) << 2)));
    }
    if (hasb) bbuf = *(const float4*)(H + (size_t)bk * HID + bc4);

    const uint32_t a_lm_base = (uint32_t)(mg * 32 + (lane & 15)) * 80 +
                               (uint32_t)(kg * 32 + ((lane >> 4) << 4));
    const uint32_t b_lm_base = (uint32_t)(kg * 16 + (lane & 15)) * 80;

#pragma unroll 1
    for (int i = 0; i < NCHUNK; i++) {
        int st = i & 1;
        uint32_t stb = sb + st * STAGE;
        __syncthreads();   // stage st free (readers of iter i-2 done)

        // ---- split + STS A (hi + lo)
#pragma unroll
        for (int p = 0; p < 4; p++) {
            int g = tid + p * 256;
            uint32_t hp0, lp0, hp1, lp1;
            split2(abuf[p].x, abuf[p].y, hp0, lp0);
            split2(abuf[p].z, abuf[p].w, hp1, lp1);
            uint32_t off = (uint32_t)(g >> 3) * 80 + (uint32_t)((g & 7) << 2) * 2;
            *(uint2*)(smem + st * STAGE + OFF_AH + off) = make_uint2(hp0, hp1);
            *(uint2*)(smem + st * STAGE + OFF_AL + off) = make_uint2(lp0, lp1);
        }
        // ---- split + STS B
        if (hasb) {
            uint32_t hp0, lp0, hp1, lp1;
            split2(bbuf.x, bbuf.y, hp0, lp0);
            split2(bbuf.z, bbuf.w, hp1, lp1);
            uint32_t off = (uint32_t)bk * 80 + (uint32_t)bc4 * 2;
            *(uint2*)(smem + st * STAGE + OFF_BH + off) = make_uint2(hp0, hp1);
            *(uint2*)(smem + st * STAGE + OFF_BL + off) = make_uint2(lp0, lp1);
        }

        // ---- prefetch chunk i+1 (latency hidden behind mma below)
        if (i + 1 < NCHUNK) {
            const float* ap = A + (i + 1) * KCH;
#pragma unroll
            for (int p = 0; p < 4; p++) {
                int g = tid + p * 256;
                abuf[p] = __ldcs((const float4*)(ap + (size_t)(g >> 3) * NN +
                                                 ((g & 7) << 2)));
            }
            if (hasb)
                bbuf = *(const float4*)(H + (size_t)((i + 1) * KCH + bk) * HID + bc4);
        }
        __syncthreads();   // stage st fully written

        // ---- B frags once per chunk (this warp's k16 half): 6 ldm_x2t
        uint32_t bh[3][2], bl[3][2];
        uint32_t brow = stb + OFF_BH + b_lm_base;
#pragma unroll
        for (int nt = 0; nt < 3; nt++) {
            ldm_x2t(bh[nt], brow + nt * 16);
            ldm_x2t(bl[nt], brow + nt * 16 + B_T);
        }
        // ---- A frags per m16 block (2 blocks), 9 MMAs each
        uint32_t aaddr = stb + OFF_AH + a_lm_base;
#pragma unroll
        for (int f = 0; f < 2; f++) {
            uint32_t ah[4], al[4];
            ldm_x4(ah, aaddr + (uint32_t)(f * 16) * 80);
            ldm_x4(al, aaddr + (uint32_t)(f * 16) * 80 + A_T);
#pragma unroll
            for (int nt = 0; nt < 3; nt++) {
                mma_bf16(acc[f][nt], ah, bh[nt]);
                mma_bf16(acc[f][nt], ah, bl[nt]);
                mma_bf16(acc[f][nt], al, bh[nt]);
            }
        }
    }

    // ---- epilogue: k-partials -> smem [kg][128][28], reduce, combine
    __syncthreads();
    {
        float* ds = (float*)smem + (size_t)kg * (128 * 28);
        int r0 = lane >> 2;
        int c0 = (lane & 3) * 2;
#pragma unroll
        for (int f = 0; f < 2; f++) {
            int rbase = mg * 32 + f * 16;
#pragma unroll
            for (int nt = 0; nt < 3; nt++) {
                int c = nt * 8 + c0;
                *(float2*)&ds[(rbase + r0) * 28 + c] =
                    make_float2(acc[f][nt][0], acc[f][nt][1]);
                *(float2*)&ds[(rbase + r0 + 8) * 28 + c] =
                    make_float2(acc[f][nt][2], acc[f][nt][3]);
            }
        }
    }
    __syncthreads();
    if (tid < TM) {
        const float* d0 = (const float*)smem + (size_t)tid * 28;
        const float* d1 = d0 + 128 * 28;
        int v = rowbase + tid;
        float ir = 1.f / (d0[20] + d1[20] + 1.f);
        const float* hsr = H + (size_t)v * HID;
        const float* h0r = &g_h[0][(size_t)bc * (NN * HID) + (size_t)v * HID];
        float* outr = &g_h[dst][(size_t)bc * (NN * HID) + (size_t)v * HID];
        float res[20];
#pragma unroll
        for (int j = 0; j < 20; j++)
            res[j] = N_ALPHA * h0r[j] + N_BETA * (d0[j] + d1[j] + hsr[j]) * ir;
#pragma unroll
        for (int q = 0; q < 5; q++)
            ((float4*)outr)[q] = make_float4(res[4 * q], res[4 * q + 1],
                                             res[4 * q + 2], res[4 * q + 3]);
    }
}

// ---------------------------------------------------------------------------
// out[bc][n][o] = sum_{p,j} h_p[bc][n][j] * We[(p*20+j)][o] + be[o]
// ---------------------------------------------------------------------------
__global__ void __launch_bounds__(256) end_kernel(const float* __restrict__ We,
                                                  const float* __restrict__ be,
                                                  float* __restrict__ out) {
    __shared__ float wsm[80 * 32];
    __shared__ float bsm[32];
    __shared__ float hsm[256 * HID];
    int tid = threadIdx.x;
    for (int i = tid; i < 80 * 32; i += 256) wsm[i] = We[i];
    if (tid < 32) bsm[tid] = be[tid];

    int r0 = blockIdx.x * 256;

    unsigned long long acc[16];
    const unsigned long long* bp = (const unsigned long long*)bsm;
#pragma unroll
    for (int p = 0; p < 4; p++) {
        __syncthreads();
        const float4* src4 = (const float4*)(&g_h[p][0] + (size_t)r0 * HID);
#pragma unroll
        for (int k = 0; k < 5; k++)
            ((float4*)hsm)[tid + k * 256] = src4[tid + k * 256];
        __syncthreads();
        if (p == 0) {
#pragma unroll
            for (int o = 0; o < 16; o++) acc[o] = bp[o];
        }
        const float* hr = hsm + tid * HID;
#pragma unroll
        for (int j = 0; j < HID; j++) {
            float v = hr[j];
            unsigned long long v2 = pack2(v, v);
            const unsigned long long* wr =
                (const unsigned long long*)&wsm[(p * HID + j) * 32];
#pragma unroll
            for (int o = 0; o < 16; o++) acc[o] = fma2(v2, wr[o], acc[o]);
        }
    }

    float* op = out + ((size_t)r0 + tid) * 32;
#pragma unroll
    for (int o = 0; o < 16; o++) {
        float2 f = unpack2(acc[o]);
        op[2 * o] = f.x; op[2 * o + 1] = f.y;
    }
}

// ---------------------------------------------------------------------------
extern "C" void kernel_launch(void* const* d_in, const int* in_sizes, int n_in,
                              void* d_out, int out_size) {
    const float* x   = (const float*)d_in[0];
    const float* adj = (const float*)d_in[1];
    const float* Ws  = (const float*)d_in[2];
    const float* bs  = (const float*)d_in[3];
    const float* We  = (const float*)d_in[4];
    const float* be  = (const float*)d_in[5];
    float* out = (float*)d_out;

    cudaFuncSetAttribute(prop_mma, cudaFuncAttributeMaxDynamicSharedMemorySize,
                         SMEM_SZ);

    dim3 pgrid(NN / TM, BC_TOT);   // (8, 128) = 1024 CTAs

    h0_kernel<<<512, 256>>>(x, Ws, bs);
    prop_mma<<<pgrid, 256, SMEM_SZ>>>(adj, 0, 1);
    prop_mma<<<pgrid, 256, SMEM_SZ>>>(adj, 1, 2);
    prop_mma<<<pgrid, 256, SMEM_SZ>>>(adj, 2, 3);
    end_kernel<<<512, 256>>>(We, be, out);
}

// round 11
// speedup vs baseline: 1.1214x; 1.0426x over previous
#include <cuda_runtime.h>
#include <cuda_bf16.h>
#include <cstdint>

#define N_ALPHA 0.05f
#define N_BETA  0.95f
#define BC_TOT  128
#define NN      1024
#define HID     20
#define KCH     32            // K per chunk
#define NCHUNK  (NN / KCH)    // 32
#define TM      128           // rows per CTA

// A tile: 128 rows x 32 bf16, rows padded to 80B -> conflict-free ldmatrix
#define A_T     (128 * 80)    // 10240 B
#define B_T     (32 * 80)     // 2560 B
#define STAGE   (2 * A_T + 2 * B_T)   // 25600
#define OFF_AH  0
#define OFF_AL  A_T
#define OFF_BH  (2 * A_T)
#define OFF_BL  (2 * A_T + B_T)
#define SMEM_SZ (2 * STAGE)   // 51200

// scratch: h0..h3
__device__ float g_h[4][BC_TOT * NN * HID];

static __device__ __forceinline__ unsigned smem_u32(const void* p) {
    unsigned a;
    asm("{ .reg .u64 t; cvta.to.shared.u64 t, %1; cvt.u32.u64 %0, t; }"
        : "=r"(a) : "l"(p));
    return a;
}
static __device__ __forceinline__ unsigned long long fma2(unsigned long long a,
                                                          unsigned long long b,
                                                          unsigned long long c) {
    unsigned long long d;
    asm("fma.rn.f32x2 %0, %1, %2, %3;" : "=l"(d) : "l"(a), "l"(b), "l"(c));
    return d;
}
static __device__ __forceinline__ unsigned long long pack2(float x, float y) {
    unsigned long long d;
    asm("mov.b64 %0, {%1, %2};" : "=l"(d) : "f"(x), "f"(y));
    return d;
}
static __device__ __forceinline__ float2 unpack2(unsigned long long v) {
    float2 f;
    asm("mov.b64 {%0, %1}, %2;" : "=f"(f.x), "=f"(f.y) : "l"(v));
    return f;
}
static __device__ __forceinline__ void ldm_x4(uint32_t* r, uint32_t addr) {
    asm volatile("ldmatrix.sync.aligned.m8n8.x4.shared.b16 {%0,%1,%2,%3}, [%4];"
                 : "=r"(r[0]), "=r"(r[1]), "=r"(r[2]), "=r"(r[3]) : "r"(addr));
}
static __device__ __forceinline__ void ldm_x2t(uint32_t* r, uint32_t addr) {
    asm volatile("ldmatrix.sync.aligned.m8n8.x2.trans.shared.b16 {%0,%1}, [%2];"
                 : "=r"(r[0]), "=r"(r[1]) : "r"(addr));
}
static __device__ __forceinline__ void mma_bf16(float* c, const uint32_t* a,
                                                const uint32_t* b) {
    asm volatile(
        "mma.sync.aligned.m16n8k16.row.col.f32.bf16.bf16.f32 "
        "{%0,%1,%2,%3}, {%4,%5,%6,%7}, {%8,%9}, {%0,%1,%2,%3};"
        : "+f"(c[0]), "+f"(c[1]), "+f"(c[2]), "+f"(c[3])
        : "r"(a[0]), "r"(a[1]), "r"(a[2]), "r"(a[3]), "r"(b[0]), "r"(b[1]));
}
// hi = truncate-to-bf16 pair; lo = exact residual rounded to bf16 pair
static __device__ __forceinline__ void split2(float x, float y,
                                              uint32_t& hp, uint32_t& lp) {
    uint32_t u0 = __float_as_uint(x), u1 = __float_as_uint(y);
    asm("prmt.b32 %0, %1, %2, 0x7632;" : "=r"(hp) : "r"(u0), "r"(u1));
    float l0 = x - __uint_as_float(u0 & 0xFFFF0000u);
    float l1 = y - __uint_as_float(u1 & 0xFFFF0000u);
    asm("cvt.rn.bf16x2.f32 %0, %1, %2;" : "=r"(lp) : "f"(l1), "f"(l0));
}

// ---------------------------------------------------------------------------
// h0[bc][n][j] = sum_i x[b][i][n][c] * Ws[i][j] + bs[j]
// ---------------------------------------------------------------------------
__global__ void h0_kernel(const float* __restrict__ x,
                          const float* __restrict__ Ws,
                          const float* __restrict__ bs) {
    __shared__ float wsm[32 * HID];
    __shared__ float bsm[HID];
    int tid = threadIdx.x;
    for (int i = tid; i < 32 * HID; i += 256) wsm[i] = Ws[i];
    if (tid < HID) bsm[tid] = bs[tid];
    __syncthreads();

    int r = blockIdx.x * 256 + tid;
    int c = r & 15;
    int n = (r >> 4) & 1023;
    int b = r >> 14;

    unsigned long long acc[10];
    const unsigned long long* bp = (const unsigned long long*)bsm;
#pragma unroll
    for (int j = 0; j < 10; j++) acc[j] = bp[j];

    const float* xp = x + (size_t)b * 32 * 16384 + n * 16 + c;
#pragma unroll
    for (int i = 0; i < 32; i++) {
        float xv = xp[(size_t)i * 16384];
        unsigned long long xv2 = pack2(xv, xv);
        const unsigned long long* wr = (const unsigned long long*)&wsm[i * HID];
#pragma unroll
        for (int j = 0; j < 10; j++) acc[j] = fma2(xv2, wr[j], acc[j]);
    }
    int bc = b * 16 + c;
    float* o = &g_h[0][((size_t)bc * NN + n) * HID];
#pragma unroll
    for (int j = 0; j < 10; j++) {
        float2 f = unpack2(acc[j]);
        o[2 * j] = f.x; o[2 * j + 1] = f.y;
    }
}

// ---------------------------------------------------------------------------
// propagation via mma.sync (bf16 hi/lo emulated fp32), software-pipelined:
//   iter i: STS chunk i+1 (regs->stage (i+1)%2), LDG chunk i+2 -> regs,
//           MMA on stage i%2 (written during iter i-1), ONE __syncthreads.
//   D[v][n<20] = sum_w adj[v][w] h[w][n] ; D[v][20] = rowsum (ones col)
//   h_dst[v] = alpha*h0[v] + beta*(D[v][:20] + h_src[v]) / (D[v][20] + 1)
// ---------------------------------------------------------------------------
__global__ void __launch_bounds__(256, 3)
prop_mma(const float* __restrict__ adj, int src, int dst) {
    extern __shared__ char smem[];
    const uint32_t sb = smem_u32(smem);
    int tid = threadIdx.x;
    int lane = tid & 31, wid = tid >> 5;
    int rowbase = blockIdx.x * TM;
    int bc = blockIdx.y;

    const float* A = adj + ((size_t)bc << 20) + ((size_t)rowbase << 10);
    const float* H = &g_h[src][(size_t)bc * (NN * HID)];

    // zero B regions (pad cols stay zero); ones col n=20 (byte 40) in Bhi
    for (int st = 0; st < 2; st++) {
        uint32_t* bb = (uint32_t*)(smem + st * STAGE + OFF_BH);
        for (int i = tid; i < (2 * B_T) / 4; i += 256) bb[i] = 0;
    }
    __syncthreads();
    if (tid < 32) {
        *(uint16_t*)(smem + 0 * STAGE + OFF_BH + tid * 80 + 40) = 0x3F80;
        *(uint16_t*)(smem + 1 * STAGE + OFF_BH + tid * 80 + 40) = 0x3F80;
    }

    bool hasb = tid < 160;
    int bk = tid / 5, bc4 = (tid % 5) * 4;

    float acc[3][4];
#pragma unroll
    for (int nt = 0; nt < 3; nt++)
#pragma unroll
        for (int q = 0; q < 4; q++) acc[nt][q] = 0.f;

    float4 abuf[4], bbuf;

    // ---- preamble: LDG chunk0, STS into stage 0, LDG chunk1, barrier
#pragma unroll
    for (int p = 0; p < 4; p++) {
        int g = tid + p * 256;
        abuf[p] = __ldcs((const float4*)(A + (size_t)(g >> 3) * NN + ((g & 7) << 2)));
    }
    if (hasb) bbuf = *(const float4*)(H + (size_t)bk * HID + bc4);

#pragma unroll
    for (int p = 0; p < 4; p++) {
        int g = tid + p * 256;
        uint32_t hp0, lp0, hp1, lp1;
        split2(abuf[p].x, abuf[p].y, hp0, lp0);
        split2(abuf[p].z, abuf[p].w, hp1, lp1);
        uint32_t off = (uint32_t)(g >> 3) * 80 + (uint32_t)((g & 7) << 2) * 2;
        *(uint2*)(smem + OFF_AH + off) = make_uint2(hp0, hp1);
        *(uint2*)(smem + OFF_AL + off) = make_uint2(lp0, lp1);
    }
    if (hasb) {
        uint32_t hp0, lp0, hp1, lp1;
        split2(bbuf.x, bbuf.y, hp0, lp0);
        split2(bbuf.z, bbuf.w, hp1, lp1);
        uint32_t off = (uint32_t)bk * 80 + (uint32_t)bc4 * 2;
        *(uint2*)(smem + OFF_BH + off) = make_uint2(hp0, hp1);
        *(uint2*)(smem + OFF_BL + off) = make_uint2(lp0, lp1);
    }
    // LDG chunk 1
#pragma unroll
    for (int p = 0; p < 4; p++) {
        int g = tid + p * 256;
        abuf[p] = __ldcs((const float4*)(A + KCH + (size_t)(g >> 3) * NN +
                                         ((g & 7) << 2)));
    }
    if (hasb) bbuf = *(const float4*)(H + (size_t)(KCH + bk) * HID + bc4);
    __syncthreads();

#pragma unroll 1
    for (int i = 0; i < NCHUNK; i++) {
        int st = i & 1;
        uint32_t stb = sb + st * STAGE;

        // ---- STS chunk i+1 (from regs) into stage (i+1)%2
        if (i + 1 < NCHUNK) {
            int nst = (i + 1) & 1;
#pragma unroll
            for (int p = 0; p < 4; p++) {
                int g = tid + p * 256;
                uint32_t hp0, lp0, hp1, lp1;
                split2(abuf[p].x, abuf[p].y, hp0, lp0);
                split2(abuf[p].z, abuf[p].w, hp1, lp1);
                uint32_t off = (uint32_t)(g >> 3) * 80 + (uint32_t)((g & 7) << 2) * 2;
                *(uint2*)(smem + nst * STAGE + OFF_AH + off) = make_uint2(hp0, hp1);
                *(uint2*)(smem + nst * STAGE + OFF_AL + off) = make_uint2(lp0, lp1);
            }
            if (hasb) {
                uint32_t hp0, lp0, hp1, lp1;
                split2(bbuf.x, bbuf.y, hp0, lp0);
                split2(bbuf.z, bbuf.w, hp1, lp1);
                uint32_t off = (uint32_t)bk * 80 + (uint32_t)bc4 * 2;
                *(uint2*)(smem + nst * STAGE + OFF_BH + off) = make_uint2(hp0, hp1);
                *(uint2*)(smem + nst * STAGE + OFF_BL + off) = make_uint2(lp0, lp1);
            }
        }
        // ---- LDG chunk i+2 -> regs (latency hides under MMA below)
        if (i + 2 < NCHUNK) {
            const float* ap = A + (i + 2) * KCH;
#pragma unroll
            for (int p = 0; p < 4; p++) {
                int g = tid + p * 256;
                abuf[p] = __ldcs((const float4*)(ap + (size_t)(g >> 3) * NN +
                                                 ((g & 7) << 2)));
            }
            if (hasb)
                bbuf = *(const float4*)(H + (size_t)((i + 2) * KCH + bk) * HID + bc4);
        }

        // ---- MMA on stage st (written during iter i-1 / preamble)
#pragma unroll
        for (int s = 0; s < 2; s++) {
            uint32_t ah[4], al[4];
            uint32_t aaddr = stb + OFF_AH +
                             (uint32_t)(wid * 16 + (lane & 15)) * 80 +
                             (uint32_t)(s * 32 + ((lane >> 4) << 4));
            ldm_x4(ah, aaddr);
            ldm_x4(al, aaddr + A_T);
            uint32_t brow = stb + OFF_BH + (uint32_t)(s * 16 + (lane & 15)) * 80;
#pragma unroll
            for (int nt = 0; nt < 3; nt++) {
                uint32_t bh[2], bl[2];
                ldm_x2t(bh, brow + nt * 16);
                ldm_x2t(bl, brow + nt * 16 + B_T);
                mma_bf16(acc[nt], ah, bh);
                mma_bf16(acc[nt], ah, bl);
                mma_bf16(acc[nt], al, bh);
            }
        }
        __syncthreads();   // single barrier: closes stage (i+1)%2 writes and
                           // stage i%2 reads before iter i+1 touches them
    }

    // ---- epilogue: D frags -> smem (rows padded to 112B), then combine
    {
        char* darea = smem + wid * (16 * 112);
        int r0 = lane >> 2;
        int cb = (lane & 3) * 2;
#pragma unroll
        for (int nt = 0; nt < 3; nt++) {
            int cbyte = (nt * 8 + cb) * 4;
            *(float2*)(darea + r0 * 112 + cbyte) = make_float2(acc[nt][0], acc[nt][1]);
            *(float2*)(darea + (r0 + 8) * 112 + cbyte) = make_float2(acc[nt][2], acc[nt][3]);
        }
    }
    __syncthreads();
    if (tid < TM) {
        const float* Drow = (const float*)(smem + (tid >> 4) * (16 * 112) +
                                           (tid & 15) * 112);
        int v = rowbase + tid;
        float ir = 1.f / (Drow[20] + 1.f);
        const float* hsr = H + (size_t)v * HID;
        const float* h0r = &g_h[0][(size_t)bc * (NN * HID) + (size_t)v * HID];
        float* outr = &g_h[dst][(size_t)bc * (NN * HID) + (size_t)v * HID];
        float res[20];
#pragma unroll
        for (int j = 0; j < 20; j++)
            res[j] = N_ALPHA * h0r[j] + N_BETA * (Drow[j] + hsr[j]) * ir;
#pragma unroll
        for (int q = 0; q < 5; q++)
            ((float4*)outr)[q] = make_float4(res[4 * q], res[4 * q + 1],
                                             res[4 * q + 2], res[4 * q + 3]);
    }
}

// ---------------------------------------------------------------------------
// out[bc][n][o] = sum_{p,j} h_p[bc][n][j] * We[(p*20+j)][o] + be[o]
// ---------------------------------------------------------------------------
__global__ void __launch_bounds__(256) end_kernel(const float* __restrict__ We,
                                                  const float* __restrict__ be,
                                                  float* __restrict__ out) {
    __shared__ float wsm[80 * 32];
    __shared__ float bsm[32];
    __shared__ float hsm[256 * HID];
    int tid = threadIdx.x;
    for (int i = tid; i < 80 * 32; i += 256) wsm[i] = We[i];
    if (tid < 32) bsm[tid] = be[tid];

    int r0 = blockIdx.x * 256;

    unsigned long long acc[16];
    const unsigned long long* bp = (const unsigned long long*)bsm;
#pragma unroll
    for (int p = 0; p < 4; p++) {
        __syncthreads();
        const float4* src4 = (const float4*)(&g_h[p][0] + (size_t)r0 * HID);
#pragma unroll
        for (int k = 0; k < 5; k++)
            ((float4*)hsm)[tid + k * 256] = src4[tid + k * 256];
        __syncthreads();
        if (p == 0) {
#pragma unroll
            for (int o = 0; o < 16; o++) acc[o] = bp[o];
        }
        const float* hr = hsm + tid * HID;
#pragma unroll
        for (int j = 0; j < HID; j++) {
            float v = hr[j];
            unsigned long long v2 = pack2(v, v);
            const unsigned long long* wr =
                (const unsigned long long*)&wsm[(p * HID + j) * 32];
#pragma unroll
            for (int o = 0; o < 16; o++) acc[o] = fma2(v2, wr[o], acc[o]);
        }
    }

    float* op = out + ((size_t)r0 + tid) * 32;
#pragma unroll
    for (int o = 0; o < 16; o++) {
        float2 f = unpack2(acc[o]);
        op[2 * o] = f.x; op[2 * o + 1] = f.y;
    }
}

// ---------------------------------------------------------------------------
extern "C" void kernel_launch(void* const* d_in, const int* in_sizes, int n_in,
                              void* d_out, int out_size) {
    const float* x   = (const float*)d_in[0];
    const float* adj = (const float*)d_in[1];
    const float* Ws  = (const float*)d_in[2];
    const float* bs  = (const float*)d_in[3];
    const float* We  = (const float*)d_in[4];
    const float* be  = (const float*)d_in[5];
    float* out = (float*)d_out;

    cudaFuncSetAttribute(prop_mma, cudaFuncAttributeMaxDynamicSharedMemorySize,
                         SMEM_SZ);

    dim3 pgrid(NN / TM, BC_TOT);   // (8, 128) = 1024 CTAs

    h0_kernel<<<512, 256>>>(x, Ws, bs);
    prop_mma<<<pgrid, 256, SMEM_SZ>>>(adj, 0, 1);
    prop_mma<<<pgrid, 256, SMEM_SZ>>>(adj, 1, 2);
    prop_mma<<<pgrid, 256, SMEM_SZ>>>(adj, 2, 3);
    end_kernel<<<512, 256>>>(We, be, out);
}

// round 12
// speedup vs baseline: 1.2273x; 1.0944x over previous
#include <cuda_runtime.h>
#include <cuda_bf16.h>
#include <cstdint>

#define N_ALPHA 0.05f
#define N_BETA  0.95f
#define BC_TOT  128
#define NN      1024
#define HID     20
#define KCH     32            // K per chunk
#define NCHUNK  (NN / KCH)    // 32
#define TM      128           // rows per CTA

// A staged RAW fp32: 128 rows x 32 fp32, rows padded to 160B (row stride = 8
// banks mod 32 -> LDS.64 fragment reads conflict-free).
// B staged as bf16 hi/lo, 80B rows (proven conflict-free for ldmatrix).
#define A_RAW   (128 * 160)   // 20480 B
#define B_T     (32 * 80)     // 2560 B
#define OFF_AR  0
#define OFF_BH  A_RAW
#define OFF_BL  (A_RAW + B_T)
#define STAGE   (A_RAW + 2 * B_T)     // 25600
#define SMEM_SZ (2 * STAGE)           // 51200

// scratch: h0..h3
__device__ float g_h[4][BC_TOT * NN * HID];

static __device__ __forceinline__ unsigned smem_u32(const void* p) {
    unsigned a;
    asm("{ .reg .u64 t; cvta.to.shared.u64 t, %1; cvt.u32.u64 %0, t; }"
        : "=r"(a) : "l"(p));
    return a;
}
static __device__ __forceinline__ void cp16(unsigned dst, const void* src) {
    asm volatile("cp.async.cg.shared.global [%0], [%1], 16;" :: "r"(dst), "l"(src));
}
static __device__ __forceinline__ unsigned long long fma2(unsigned long long a,
                                                          unsigned long long b,
                                                          unsigned long long c) {
    unsigned long long d;
    asm("fma.rn.f32x2 %0, %1, %2, %3;" : "=l"(d) : "l"(a), "l"(b), "l"(c));
    return d;
}
static __device__ __forceinline__ unsigned long long pack2(float x, float y) {
    unsigned long long d;
    asm("mov.b64 %0, {%1, %2};" : "=l"(d) : "f"(x), "f"(y));
    return d;
}
static __device__ __forceinline__ float2 unpack2(unsigned long long v) {
    float2 f;
    asm("mov.b64 {%0, %1}, %2;" : "=f"(f.x), "=f"(f.y) : "l"(v));
    return f;
}
static __device__ __forceinline__ float2 lds64(uint32_t addr) {
    float2 v;
    asm volatile("ld.shared.v2.f32 {%0,%1}, [%2];"
                 : "=f"(v.x), "=f"(v.y) : "r"(addr));
    return v;
}
static __device__ __forceinline__ void ldm_x2t(uint32_t* r, uint32_t addr) {
    asm volatile("ldmatrix.sync.aligned.m8n8.x2.trans.shared.b16 {%0,%1}, [%2];"
                 : "=r"(r[0]), "=r"(r[1]) : "r"(addr));
}
static __device__ __forceinline__ void mma_bf16(float* c, const uint32_t* a,
                                                const uint32_t* b) {
    asm volatile(
        "mma.sync.aligned.m16n8k16.row.col.f32.bf16.bf16.f32 "
        "{%0,%1,%2,%3}, {%4,%5,%6,%7}, {%8,%9}, {%0,%1,%2,%3};"
        : "+f"(c[0]), "+f"(c[1]), "+f"(c[2]), "+f"(c[3])
        : "r"(a[0]), "r"(a[1]), "r"(a[2]), "r"(a[3]), "r"(b[0]), "r"(b[1]));
}
// hi = truncate-to-bf16 pair; lo = exact residual rounded to bf16 pair
static __device__ __forceinline__ void split2(float x, float y,
                                              uint32_t& hp, uint32_t& lp) {
    uint32_t u0 = __float_as_uint(x), u1 = __float_as_uint(y);
    asm("prmt.b32 %0, %1, %2, 0x7632;" : "=r"(hp) : "r"(u0), "r"(u1));
    float l0 = x - __uint_as_float(u0 & 0xFFFF0000u);
    float l1 = y - __uint_as_float(u1 & 0xFFFF0000u);
    asm("cvt.rn.bf16x2.f32 %0, %1, %2;" : "=r"(lp) : "f"(l1), "f"(l0));
}

// ---------------------------------------------------------------------------
// h0[bc][n][j] = sum_i x[b][i][n][c] * Ws[i][j] + bs[j]
// ---------------------------------------------------------------------------
__global__ void h0_kernel(const float* __restrict__ x,
                          const float* __restrict__ Ws,
                          const float* __restrict__ bs) {
    __shared__ float wsm[32 * HID];
    __shared__ float bsm[HID];
    int tid = threadIdx.x;
    for (int i = tid; i < 32 * HID; i += 256) wsm[i] = Ws[i];
    if (tid < HID) bsm[tid] = bs[tid];
    __syncthreads();

    int r = blockIdx.x * 256 + tid;
    int c = r & 15;
    int n = (r >> 4) & 1023;
    int b = r >> 14;

    unsigned long long acc[10];
    const unsigned long long* bp = (const unsigned long long*)bsm;
#pragma unroll
    for (int j = 0; j < 10; j++) acc[j] = bp[j];

    const float* xp = x + (size_t)b * 32 * 16384 + n * 16 + c;
#pragma unroll
    for (int i = 0; i < 32; i++) {
        float xv = xp[(size_t)i * 16384];
        unsigned long long xv2 = pack2(xv, xv);
        const unsigned long long* wr = (const unsigned long long*)&wsm[i * HID];
#pragma unroll
        for (int j = 0; j < 10; j++) acc[j] = fma2(xv2, wr[j], acc[j]);
    }
    int bc = b * 16 + c;
    float* o = &g_h[0][((size_t)bc * NN + n) * HID];
#pragma unroll
    for (int j = 0; j < 10; j++) {
        float2 f = unpack2(acc[j]);
        o[2 * j] = f.x; o[2 * j + 1] = f.y;
    }
}

// ---------------------------------------------------------------------------
// propagation via mma.sync (bf16 hi/lo emulated fp32).
// A staged raw fp32 by cp.async.cg (no LDG->reg->STS round trip); hi/lo split
// happens at consume time from LDS.64 (each element consumed by one warp).
// B staged producer-split bf16 (tiny), consumed via ldmatrix (R7 path).
//   D[v][n<20] = sum_w adj[v][w] h[w][n] ; D[v][20] = rowsum (ones col)
//   h_dst[v] = alpha*h0[v] + beta*(D[v][:20] + h_src[v]) / (D[v][20] + 1)
// ---------------------------------------------------------------------------
__global__ void __launch_bounds__(256, 4)
prop_mma(const float* __restrict__ adj, int src, int dst) {
    extern __shared__ char smem[];
    const uint32_t sb = smem_u32(smem);
    int tid = threadIdx.x;
    int lane = tid & 31, wid = tid >> 5;
    int rowbase = blockIdx.x * TM;
    int bc = blockIdx.y;

    const float* A = adj + ((size_t)bc << 20) + ((size_t)rowbase << 10);
    const float* H = &g_h[src][(size_t)bc * (NN * HID)];

    // zero B regions (pad cols 21..39 stay zero); ones col n=20 (byte 40) in Bhi
    for (int st = 0; st < 2; st++) {
        uint32_t* bb = (uint32_t*)(smem + st * STAGE + OFF_BH);
        for (int i = tid; i < (2 * B_T) / 4; i += 256) bb[i] = 0;
    }
    __syncthreads();
    if (tid < 32) {
        *(uint16_t*)(smem + 0 * STAGE + OFF_BH + tid * 80 + 40) = 0x3F80;
        *(uint16_t*)(smem + 1 * STAGE + OFF_BH + tid * 80 + 40) = 0x3F80;
    }

    bool hasb = tid < 160;
    int bk = tid / 5, bc4 = (tid % 5) * 4;

    float acc[3][4];
#pragma unroll
    for (int nt = 0; nt < 3; nt++)
#pragma unroll
        for (int q = 0; q < 4; q++) acc[nt][q] = 0.f;

    // ---- preamble: A chunk0 via cp.async -> stage0; B0 STS; B1 -> regs
#pragma unroll
    for (int p = 0; p < 4; p++) {
        int g = tid + p * 256;               // 1024 granules of 16B
        int row = g >> 3, q = g & 7;
        cp16(sb + OFF_AR + (uint32_t)row * 160 + (uint32_t)q * 16,
             A + (size_t)row * NN + q * 4);
    }
    asm volatile("cp.async.commit_group;");
    float4 bbuf;
    if (hasb) {
        float4 b0 = *(const float4*)(H + (size_t)bk * HID + bc4);
        uint32_t hp0, lp0, hp1, lp1;
        split2(b0.x, b0.y, hp0, lp0);
        split2(b0.z, b0.w, hp1, lp1);
        uint32_t off = (uint32_t)bk * 80 + (uint32_t)bc4 * 2;
        *(uint2*)(smem + OFF_BH + off) = make_uint2(hp0, hp1);
        *(uint2*)(smem + OFF_BL + off) = make_uint2(lp0, lp1);
        bbuf = *(const float4*)(H + (size_t)(KCH + bk) * HID + bc4);
    }

    const uint32_t a_frag_base = (uint32_t)(wid * 16 + (lane >> 2)) * 160 +
                                 (uint32_t)((lane & 3) * 2) * 4;
    const uint32_t b_lm_base = (uint32_t)(lane & 15) * 80;

#pragma unroll 1
    for (int i = 0; i < NCHUNK; i++) {
        int st = i & 1, nst = (i + 1) & 1;
        uint32_t stb = sb + st * STAGE;

        asm volatile("cp.async.wait_group 0;");
        __syncthreads();   // stage st visible to all; stage nst free (iter i-1 done)

        if (i + 1 < NCHUNK) {
            // A chunk i+1 -> stage nst (async)
            const float* ap = A + (i + 1) * KCH;
#pragma unroll
            for (int p = 0; p < 4; p++) {
                int g = tid + p * 256;
                int row = g >> 3, q = g & 7;
                cp16(sb + nst * STAGE + OFF_AR + (uint32_t)row * 160 +
                         (uint32_t)q * 16,
                     ap + (size_t)row * NN + q * 4);
            }
            asm volatile("cp.async.commit_group;");
            // B chunk i+1 -> stage nst (from regs), prefetch B chunk i+2
            if (hasb) {
                uint32_t hp0, lp0, hp1, lp1;
                split2(bbuf.x, bbuf.y, hp0, lp0);
                split2(bbuf.z, bbuf.w, hp1, lp1);
                uint32_t off = (uint32_t)bk * 80 + (uint32_t)bc4 * 2;
                *(uint2*)(smem + nst * STAGE + OFF_BH + off) = make_uint2(hp0, hp1);
                *(uint2*)(smem + nst * STAGE + OFF_BL + off) = make_uint2(lp0, lp1);
                if (i + 2 < NCHUNK)
                    bbuf = *(const float4*)(H + (size_t)((i + 2) * KCH + bk) * HID + bc4);
            }
        }

        // ---- consume stage st: LDS.64 raw A -> split -> frags; B via ldmatrix
#pragma unroll
        for (int s = 0; s < 2; s++) {
            uint32_t abase = stb + OFF_AR + a_frag_base + (uint32_t)(s * 16) * 4;
            float2 f00 = lds64(abase);                    // (r,     c..c+1)
            float2 f10 = lds64(abase + 8 * 160);          // (r+8,   c..c+1)
            float2 f01 = lds64(abase + 8 * 4);            // (r,     c+8..c+9)
            float2 f11 = lds64(abase + 8 * 160 + 8 * 4);  // (r+8,   c+8..c+9)
            uint32_t ah[4], al[4];
            split2(f00.x, f00.y, ah[0], al[0]);
            split2(f10.x, f10.y, ah[1], al[1]);
            split2(f01.x, f01.y, ah[2], al[2]);
            split2(f11.x, f11.y, ah[3], al[3]);
            uint32_t brow = stb + OFF_BH + b_lm_base + (uint32_t)(s * 16) * 80;
#pragma unroll
            for (int nt = 0; nt < 3; nt++) {
                uint32_t bh[2], bl[2];
                ldm_x2t(bh, brow + nt * 16);
                ldm_x2t(bl, brow + nt * 16 + B_T);
                mma_bf16(acc[nt], ah, bh);
                mma_bf16(acc[nt], ah, bl);
                mma_bf16(acc[nt], al, bh);
            }
        }
    }

    // ---- epilogue: D frags -> smem (rows padded to 112B), then combine
    __syncthreads();
    {
        char* darea = smem + wid * (16 * 112);
        int r0 = lane >> 2;
        int cb = (lane & 3) * 2;
#pragma unroll
        for (int nt = 0; nt < 3; nt++) {
            int cbyte = (nt * 8 + cb) * 4;
            *(float2*)(darea + r0 * 112 + cbyte) = make_float2(acc[nt][0], acc[nt][1]);
            *(float2*)(darea + (r0 + 8) * 112 + cbyte) = make_float2(acc[nt][2], acc[nt][3]);
        }
    }
    __syncthreads();
    if (tid < TM) {
        const float* Drow = (const float*)(smem + (tid >> 4) * (16 * 112) +
                                           (tid & 15) * 112);
        int v = rowbase + tid;
        float ir = 1.f / (Drow[20] + 1.f);
        const float* hsr = H + (size_t)v * HID;
        const float* h0r = &g_h[0][(size_t)bc * (NN * HID) + (size_t)v * HID];
        float* outr = &g_h[dst][(size_t)bc * (NN * HID) + (size_t)v * HID];
        float res[20];
#pragma unroll
        for (int j = 0; j < 20; j++)
            res[j] = N_ALPHA * h0r[j] + N_BETA * (Drow[j] + hsr[j]) * ir;
#pragma unroll
        for (int q = 0; q < 5; q++)
            ((float4*)outr)[q] = make_float4(res[4 * q], res[4 * q + 1],
                                             res[4 * q + 2], res[4 * q + 3]);
    }
}

// ---------------------------------------------------------------------------
// out[bc][n][o] = sum_{p,j} h_p[bc][n][j] * We[(p*20+j)][o] + be[o]
// ---------------------------------------------------------------------------
__global__ void __launch_bounds__(256) end_kernel(const float* __restrict__ We,
                                                  const float* __restrict__ be,
                                                  float* __restrict__ out) {
    __shared__ float wsm[80 * 32];
    __shared__ float bsm[32];
    __shared__ float hsm[256 * HID];
    int tid = threadIdx.x;
    for (int i = tid; i < 80 * 32; i += 256) wsm[i] = We[i];
    if (tid < 32) bsm[tid] = be[tid];

    int r0 = blockIdx.x * 256;

    unsigned long long acc[16];
    const unsigned long long* bp = (const unsigned long long*)bsm;
#pragma unroll
    for (int p = 0; p < 4; p++) {
        __syncthreads();
        const float4* src4 = (const float4*)(&g_h[p][0] + (size_t)r0 * HID);
#pragma unroll
        for (int k = 0; k < 5; k++)
            ((float4*)hsm)[tid + k * 256] = src4[tid + k * 256];
        __syncthreads();
        if (p == 0) {
#pragma unroll
            for (int o = 0; o < 16; o++) acc[o] = bp[o];
        }
        const float* hr = hsm + tid * HID;
#pragma unroll
        for (int j = 0; j < HID; j++) {
            float v = hr[j];
            unsigned long long v2 = pack2(v, v);
            const unsigned long long* wr =
                (const unsigned long long*)&wsm[(p * HID + j) * 32];
#pragma unroll
            for (int o = 0; o < 16; o++) acc[o] = fma2(v2, wr[o], acc[o]);
        }
    }

    float* op = out + ((size_t)r0 + tid) * 32;
#pragma unroll
    for (int o = 0; o < 16; o++) {
        float2 f = unpack2(acc[o]);
        op[2 * o] = f.x; op[2 * o + 1] = f.y;
    }
}

// ---------------------------------------------------------------------------
extern "C" void kernel_launch(void* const* d_in, const int* in_sizes, int n_in,
                              void* d_out, int out_size) {
    const float* x   = (const float*)d_in[0];
    const float* adj = (const float*)d_in[1];
    const float* Ws  = (const float*)d_in[2];
    const float* bs  = (const float*)d_in[3];
    const float* We  = (const float*)d_in[4];
    const float* be  = (const float*)d_in[5];
    float* out = (float*)d_out;

    cudaFuncSetAttribute(prop_mma, cudaFuncAttributeMaxDynamicSharedMemorySize,
                         SMEM_SZ);

    dim3 pgrid(NN / TM, BC_TOT);   // (8, 128) = 1024 CTAs

    h0_kernel<<<512, 256>>>(x, Ws, bs);
    prop_mma<<<pgrid, 256, SMEM_SZ>>>(adj, 0, 1);
    prop_mma<<<pgrid, 256, SMEM_SZ>>>(adj, 1, 2);
    prop_mma<<<pgrid, 256, SMEM_SZ>>>(adj, 2, 3);
    end_kernel<<<512, 256>>>(We, be, out);
}